// round 1
// baseline (speedup 1.0000x reference)
#include <cuda_runtime.h>
#include <cuda_bf16.h>

#define ROWS_PER_BLOCK 8

__device__ __forceinline__ float warp_sum(float v) {
    #pragma unroll
    for (int o = 16; o > 0; o >>= 1)
        v += __shfl_xor_sync(0xFFFFFFFFu, v, o);
    return v;
}

__global__ __launch_bounds__(ROWS_PER_BLOCK * 32)
void smf_kernel(const float* __restrict__ X,
                const float* __restrict__ theta,
                const float* __restrict__ f_bias,
                const float* __restrict__ xi,
                const float* __restrict__ g_bias,
                float* __restrict__ out,
                int N)
{
    __shared__ float2 Vs[ROWS_PER_BLOCK + 1];

    const int warp = threadIdx.x >> 5;
    const int lane = threadIdx.x & 31;

    const int i  = blockIdx.x * ROWS_PER_BLOCK + warp;      // this warp's row
    const int in = (i + 1 == N) ? 0 : (i + 1);              // circulant next row

    // Per-lane float4 slices (D=128 -> 32 lanes x 4 floats)
    const float4 x   = reinterpret_cast<const float4*>(X     + (size_t)i  * 128)[lane];
    const float4 t   = reinterpret_cast<const float4*>(theta + (size_t)i  * 128)[lane];
    const float4 tn  = reinterpret_cast<const float4*>(theta + (size_t)in * 128)[lane];
    const float4 xi0 = reinterpret_cast<const float4*>(xi)[lane];
    const float4 xi1 = reinterpret_cast<const float4*>(xi + 128)[lane];

    float pd = x.x*t.x   + x.y*t.y   + x.z*t.z   + x.w*t.w;
    float ps = x.x*tn.x  + x.y*tn.y  + x.z*tn.z  + x.w*tn.w;
    float g0 = x.x*xi0.x + x.y*xi0.y + x.z*xi0.z + x.w*xi0.w;
    float g1 = x.x*xi1.x + x.y*xi1.y + x.z*xi1.z + x.w*xi1.w;

    pd = warp_sum(pd);
    ps = warp_sum(ps);
    g0 = warp_sum(g0);
    g1 = warp_sum(g1);

    const float gb0 = g_bias[0];
    const float gb1 = g_bias[1];

    // V[i] for this warp's row
    if (lane == 0) {
        Vs[warp] = make_float2(fmaxf(g0 + gb0, 0.0f), fmaxf(g1 + gb1, 0.0f));
    }

    // Halo: last warp also computes V[row_base + ROWS_PER_BLOCK] = V[in] for warp 7
    if (warp == ROWS_PER_BLOCK - 1) {
        const float4 xh = reinterpret_cast<const float4*>(X + (size_t)in * 128)[lane];
        float h0 = xh.x*xi0.x + xh.y*xi0.y + xh.z*xi0.z + xh.w*xi0.w;
        float h1 = xh.x*xi1.x + xh.y*xi1.y + xh.z*xi1.z + xh.w*xi1.w;
        h0 = warp_sum(h0);
        h1 = warp_sum(h1);
        if (lane == 0) {
            Vs[ROWS_PER_BLOCK] = make_float2(fmaxf(h0 + gb0, 0.0f),
                                             fmaxf(h1 + gb1, 0.0f));
        }
    }

    __syncthreads();

    if (lane == 0) {
        const float wd = fmaxf(pd + f_bias[i],  0.0f);
        const float ws = fmaxf(ps + f_bias[in], 0.0f);
        const float2 vi = Vs[warp];
        const float2 vn = Vs[warp + 1];
        float2 r;
        r.x = wd * vi.x + ws * vn.x;
        r.y = wd * vi.y + ws * vn.y;
        reinterpret_cast<float2*>(out)[i] = r;
    }
}

extern "C" void kernel_launch(void* const* d_in, const int* in_sizes, int n_in,
                              void* d_out, int out_size)
{
    const float* X      = (const float*)d_in[0];
    const float* theta  = (const float*)d_in[1];
    const float* f_bias = (const float*)d_in[2];
    const float* xi     = (const float*)d_in[3];
    const float* g_bias = (const float*)d_in[4];
    float* out = (float*)d_out;

    const int N = in_sizes[2];                 // f_bias has N elements
    const int blocks = N / ROWS_PER_BLOCK;     // N = 524288, divisible by 8

    smf_kernel<<<blocks, ROWS_PER_BLOCK * 32>>>(X, theta, f_bias, xi, g_bias, out, N);
}

// round 2
// speedup vs baseline: 1.1195x; 1.1195x over previous
#include <cuda_runtime.h>
#include <cuda_bf16.h>

#define WARPS_PER_BLOCK 8
#define ROWS_PER_WARP 4
#define ROWS_PER_BLOCK (WARPS_PER_BLOCK * ROWS_PER_WARP)   // 32

__device__ __forceinline__ float warp_sum(float v) {
    #pragma unroll
    for (int o = 16; o > 0; o >>= 1)
        v += __shfl_xor_sync(0xFFFFFFFFu, v, o);
    return v;
}

__device__ __forceinline__ float dot4(float4 a, float4 b) {
    return a.x*b.x + a.y*b.y + a.z*b.z + a.w*b.w;
}

__global__ __launch_bounds__(WARPS_PER_BLOCK * 32)
void smf_kernel(const float* __restrict__ X,
                const float* __restrict__ theta,
                const float* __restrict__ f_bias,
                const float* __restrict__ xi,
                const float* __restrict__ g_bias,
                float* __restrict__ out,
                int N)
{
    __shared__ float2 Vs[ROWS_PER_BLOCK + 1];

    const int warp = threadIdx.x >> 5;
    const int lane = threadIdx.x & 31;

    const int base = (blockIdx.x * WARPS_PER_BLOCK + warp) * ROWS_PER_WARP;

    const float4* X4  = reinterpret_cast<const float4*>(X);
    const float4* T4  = reinterpret_cast<const float4*>(theta);
    const float4* XI4 = reinterpret_cast<const float4*>(xi);

    // ---- Front-load everything (max MLP) ----
    float4 x[ROWS_PER_WARP];
    #pragma unroll
    for (int r = 0; r < ROWS_PER_WARP; r++)
        x[r] = X4[(size_t)(base + r) * 32 + lane];

    float4 t[ROWS_PER_WARP + 1];
    #pragma unroll
    for (int r = 0; r <= ROWS_PER_WARP; r++) {
        int row = base + r;
        if (row == N) row = 0;            // only possible at r==ROWS_PER_WARP
        t[r] = T4[(size_t)row * 32 + lane];
    }

    const float4 xi0 = XI4[lane];
    const float4 xi1 = XI4[32 + lane];

    // Halo X row (only warp 7 uses it, but load uniformly costs little; predicate it)
    float4 xh;
    int hrow = base + ROWS_PER_WARP;
    if (hrow == N) hrow = 0;
    const bool halo = (warp == WARPS_PER_BLOCK - 1);
    if (halo)
        xh = X4[(size_t)hrow * 32 + lane];

    // ---- Per-lane dot partials ----
    float pd[ROWS_PER_WARP], ps[ROWS_PER_WARP], g0[ROWS_PER_WARP], g1[ROWS_PER_WARP];
    #pragma unroll
    for (int r = 0; r < ROWS_PER_WARP; r++) {
        pd[r] = dot4(x[r], t[r]);
        ps[r] = dot4(x[r], t[r + 1]);
        g0[r] = dot4(x[r], xi0);
        g1[r] = dot4(x[r], xi1);
    }

    // ---- Reductions ----
    #pragma unroll
    for (int r = 0; r < ROWS_PER_WARP; r++) {
        pd[r] = warp_sum(pd[r]);
        ps[r] = warp_sum(ps[r]);
        g0[r] = warp_sum(g0[r]);
        g1[r] = warp_sum(g1[r]);
    }

    const float gb0 = g_bias[0];
    const float gb1 = g_bias[1];

    if (lane == 0) {
        #pragma unroll
        for (int r = 0; r < ROWS_PER_WARP; r++)
            Vs[warp * ROWS_PER_WARP + r] =
                make_float2(fmaxf(g0[r] + gb0, 0.0f), fmaxf(g1[r] + gb1, 0.0f));
    }

    if (halo) {
        float h0 = warp_sum(dot4(xh, xi0));
        float h1 = warp_sum(dot4(xh, xi1));
        if (lane == 0)
            Vs[ROWS_PER_BLOCK] = make_float2(fmaxf(h0 + gb0, 0.0f),
                                             fmaxf(h1 + gb1, 0.0f));
    }

    __syncthreads();

    if (lane == 0) {
        #pragma unroll
        for (int r = 0; r < ROWS_PER_WARP; r++) {
            const int i = base + r;
            int in = i + 1;
            if (in == N) in = 0;
            const float wd = fmaxf(pd[r] + f_bias[i],  0.0f);
            const float ws = fmaxf(ps[r] + f_bias[in], 0.0f);
            const float2 vi = Vs[warp * ROWS_PER_WARP + r];
            const float2 vn = Vs[warp * ROWS_PER_WARP + r + 1];
            float2 o;
            o.x = wd * vi.x + ws * vn.x;
            o.y = wd * vi.y + ws * vn.y;
            reinterpret_cast<float2*>(out)[i] = o;
        }
    }
}

extern "C" void kernel_launch(void* const* d_in, const int* in_sizes, int n_in,
                              void* d_out, int out_size)
{
    const float* X      = (const float*)d_in[0];
    const float* theta  = (const float*)d_in[1];
    const float* f_bias = (const float*)d_in[2];
    const float* xi     = (const float*)d_in[3];
    const float* g_bias = (const float*)d_in[4];
    float* out = (float*)d_out;

    const int N = in_sizes[2];                  // f_bias has N elements
    const int blocks = N / ROWS_PER_BLOCK;      // 524288 / 32 = 16384

    smf_kernel<<<blocks, WARPS_PER_BLOCK * 32>>>(X, theta, f_bias, xi, g_bias, out, N);
}

// round 3
// speedup vs baseline: 1.2128x; 1.0833x over previous
#include <cuda_runtime.h>
#include <cuda_bf16.h>

#define WARPS_PER_BLOCK 8
#define ROWS_PER_WARP 8
#define ROWS_PER_BLOCK (WARPS_PER_BLOCK * ROWS_PER_WARP)   // 64

__device__ __forceinline__ float warp_sum(float v) {
    #pragma unroll
    for (int o = 16; o > 0; o >>= 1)
        v += __shfl_xor_sync(0xFFFFFFFFu, v, o);
    return v;
}

__device__ __forceinline__ float dot4(float4 a, float4 b) {
    return a.x*b.x + a.y*b.y + a.z*b.z + a.w*b.w;
}

__global__ __launch_bounds__(WARPS_PER_BLOCK * 32)
void smf_kernel(const float* __restrict__ X,
                const float* __restrict__ theta,
                const float* __restrict__ f_bias,
                const float* __restrict__ xi,
                const float* __restrict__ g_bias,
                float* __restrict__ out,
                int N)
{
    __shared__ float2 Vfirst[WARPS_PER_BLOCK];   // V of each warp's first row

    const int warp = threadIdx.x >> 5;
    const int lane = threadIdx.x & 31;
    const int base = (blockIdx.x * WARPS_PER_BLOCK + warp) * ROWS_PER_WARP;

    const float4* __restrict__ X4  = reinterpret_cast<const float4*>(X);
    const float4* __restrict__ T4  = reinterpret_cast<const float4*>(theta);
    const float4* __restrict__ XI4 = reinterpret_cast<const float4*>(xi);

    const float4 xi0 = XI4[lane];
    const float4 xi1 = XI4[32 + lane];
    const float gb0 = g_bias[0];
    const float gb1 = g_bias[1];

    // Pipeline state: current X row, current theta (diag), next theta (sup)
    float4 x_cur = X4[(size_t)base * 32 + lane];
    float4 t_cur = T4[(size_t)base * 32 + lane];
    float4 t_nxt = T4[(size_t)(base + 1) * 32 + lane];

    float wd_p = 0.0f, ws_p = 0.0f, v0_p = 0.0f, v1_p = 0.0f;

    #pragma unroll
    for (int r = 0; r < ROWS_PER_WARP; r++) {
        const int row = base + r;

        // Prefetch next iteration's x and theta (distance 1)
        float4 x_nx, t_nx2;
        if (r < ROWS_PER_WARP - 1) {
            x_nx = X4[(size_t)(row + 1) * 32 + lane];
            int n2 = row + 2;
            if (n2 >= N) n2 -= N;                  // only at grid tail
            t_nx2 = T4[(size_t)n2 * 32 + lane];
        }

        // Four independent reductions (pipelined butterflies)
        float pd = warp_sum(dot4(x_cur, t_cur));
        float ps = warp_sum(dot4(x_cur, t_nxt));
        float q0 = warp_sum(dot4(x_cur, xi0));
        float q1 = warp_sum(dot4(x_cur, xi1));

        int rn = row + 1;
        if (rn >= N) rn -= N;
        const float wd = fmaxf(pd + f_bias[row], 0.0f);
        const float ws = fmaxf(ps + f_bias[rn],  0.0f);
        const float v0 = fmaxf(q0 + gb0, 0.0f);
        const float v1 = fmaxf(q1 + gb1, 0.0f);

        if (r == 0) {
            if (lane == 0)
                Vfirst[warp] = make_float2(v0, v1);
        } else if (lane == 0) {
            float2 o;
            o.x = wd_p * v0_p + ws_p * v0;
            o.y = wd_p * v1_p + ws_p * v1;
            reinterpret_cast<float2*>(out)[row - 1] = o;
        }

        wd_p = wd; ws_p = ws; v0_p = v0; v1_p = v1;
        if (r < ROWS_PER_WARP - 1) {
            x_cur = x_nx;
            t_cur = t_nxt;
            t_nxt = t_nx2;
        }
    }

    // Final row of this warp needs V[base + ROWS_PER_WARP]
    float2 vnext = make_float2(0.0f, 0.0f);
    if (warp == WARPS_PER_BLOCK - 1) {
        int h = base + ROWS_PER_WARP;
        if (h >= N) h -= N;
        const float4 xh = X4[(size_t)h * 32 + lane];
        float h0 = warp_sum(dot4(xh, xi0));
        float h1 = warp_sum(dot4(xh, xi1));
        vnext = make_float2(fmaxf(h0 + gb0, 0.0f), fmaxf(h1 + gb1, 0.0f));
    }
    __syncthreads();

    if (lane == 0) {
        if (warp < WARPS_PER_BLOCK - 1)
            vnext = Vfirst[warp + 1];
        float2 o;
        o.x = wd_p * v0_p + ws_p * vnext.x;
        o.y = wd_p * v1_p + ws_p * vnext.y;
        reinterpret_cast<float2*>(out)[base + ROWS_PER_WARP - 1] = o;
    }
}

extern "C" void kernel_launch(void* const* d_in, const int* in_sizes, int n_in,
                              void* d_out, int out_size)
{
    const float* X      = (const float*)d_in[0];
    const float* theta  = (const float*)d_in[1];
    const float* f_bias = (const float*)d_in[2];
    const float* xi     = (const float*)d_in[3];
    const float* g_bias = (const float*)d_in[4];
    float* out = (float*)d_out;

    const int N = in_sizes[2];                   // f_bias has N elements
    const int blocks = N / ROWS_PER_BLOCK;       // 524288 / 64 = 8192

    smf_kernel<<<blocks, WARPS_PER_BLOCK * 32>>>(X, theta, f_bias, xi, g_bias, out, N);
}

// round 4
// speedup vs baseline: 1.2873x; 1.0615x over previous
#include <cuda_runtime.h>
#include <cuda_bf16.h>

#define WARPS_PER_BLOCK 8
#define ROWS_PER_WARP 8
#define ROWS_PER_BLOCK (WARPS_PER_BLOCK * ROWS_PER_WARP)   // 64

__device__ __forceinline__ float dot4(float4 a, float4 b) {
    return a.x*b.x + a.y*b.y + a.z*b.z + a.w*b.w;
}

// Packed reduction of 4 per-lane values across the warp.
// Returns all 4 totals broadcast to every lane. 10 SHFL total.
__device__ __forceinline__ void quad_reduce(float pd, float ps, float q0, float q1,
                                            int lane,
                                            float& PD, float& PS, float& Q0, float& Q1)
{
    const unsigned FULL = 0xFFFFFFFFu;
    const bool lo16 = (lane & 16) == 0;

    // Stage 1 (XOR 16): low half accumulates {pd,ps}, high half {q0,q1}
    float a  = lo16 ? q0 : pd;
    float b  = lo16 ? q1 : ps;
    float ra = __shfl_xor_sync(FULL, a, 16);
    float rb = __shfl_xor_sync(FULL, b, 16);
    float u  = (lo16 ? pd : q0) + ra;
    float v  = (lo16 ? ps : q1) + rb;

    // Stage 2 (XOR 8): each 8-lane group owns one value
    const bool lo8 = (lane & 8) == 0;
    float c  = lo8 ? v : u;
    float rc = __shfl_xor_sync(FULL, c, 8);
    float s  = (lo8 ? u : v) + rc;

    // Stages 3-5: butterfly within the 8-lane group
    s += __shfl_xor_sync(FULL, s, 4);
    s += __shfl_xor_sync(FULL, s, 2);
    s += __shfl_xor_sync(FULL, s, 1);

    // Gather: group bases 0/8/16/24 hold pd/ps/q0/q1
    PD = __shfl_sync(FULL, s, 0);
    PS = __shfl_sync(FULL, s, 8);
    Q0 = __shfl_sync(FULL, s, 16);
    Q1 = __shfl_sync(FULL, s, 24);
}

__global__ __launch_bounds__(WARPS_PER_BLOCK * 32)
void smf_kernel(const float* __restrict__ X,
                const float* __restrict__ theta,
                const float* __restrict__ f_bias,
                const float* __restrict__ xi,
                const float* __restrict__ g_bias,
                float* __restrict__ out,
                int N)
{
    __shared__ float2 Vfirst[WARPS_PER_BLOCK];   // V of each warp's first row

    const int warp = threadIdx.x >> 5;
    const int lane = threadIdx.x & 31;
    const int base = (blockIdx.x * WARPS_PER_BLOCK + warp) * ROWS_PER_WARP;

    const float4* __restrict__ X4  = reinterpret_cast<const float4*>(X);
    const float4* __restrict__ T4  = reinterpret_cast<const float4*>(theta);
    const float4* __restrict__ XI4 = reinterpret_cast<const float4*>(xi);

    const float4 xi0 = XI4[lane];
    const float4 xi1 = XI4[32 + lane];
    const float gb0 = g_bias[0];
    const float gb1 = g_bias[1];

    // Pipeline state: current X row, current theta (diag), next theta (sup)
    float4 x_cur = X4[(size_t)base * 32 + lane];
    float4 t_cur = T4[(size_t)base * 32 + lane];
    float4 t_nxt = T4[(size_t)(base + 1) * 32 + lane];
    float  fb_cur = __ldg(f_bias + base);

    float wd_p = 0.0f, ws_p = 0.0f, v0_p = 0.0f, v1_p = 0.0f;

    #pragma unroll
    for (int r = 0; r < ROWS_PER_WARP; r++) {
        const int row = base + r;
        int rn = row + 1;
        if (rn >= N) rn -= N;

        // Prefetch next iteration's x and theta (distance 1)
        float4 x_nx, t_nx2;
        if (r < ROWS_PER_WARP - 1) {
            x_nx = X4[(size_t)(row + 1) * 32 + lane];
            int n2 = row + 2;
            if (n2 >= N) n2 -= N;
            t_nx2 = T4[(size_t)n2 * 32 + lane];
        }
        const float fb_nxt = __ldg(f_bias + rn);

        // Per-lane partials for the 4 dot products
        float pd = dot4(x_cur, t_cur);
        float ps = dot4(x_cur, t_nxt);
        float q0 = dot4(x_cur, xi0);
        float q1 = dot4(x_cur, xi1);

        float PD, PS, Q0, Q1;
        quad_reduce(pd, ps, q0, q1, lane, PD, PS, Q0, Q1);

        const float wd = fmaxf(PD + fb_cur, 0.0f);
        const float ws = fmaxf(PS + fb_nxt, 0.0f);
        const float v0 = fmaxf(Q0 + gb0, 0.0f);
        const float v1 = fmaxf(Q1 + gb1, 0.0f);

        if (r == 0) {
            if (lane == 0)
                Vfirst[warp] = make_float2(v0, v1);
        } else if (lane == 0) {
            float2 o;
            o.x = wd_p * v0_p + ws_p * v0;
            o.y = wd_p * v1_p + ws_p * v1;
            reinterpret_cast<float2*>(out)[row - 1] = o;
        }

        wd_p = wd; ws_p = ws; v0_p = v0; v1_p = v1;
        fb_cur = fb_nxt;
        if (r < ROWS_PER_WARP - 1) {
            x_cur = x_nx;
            t_cur = t_nxt;
            t_nxt = t_nx2;
        }
    }

    // Final row of this warp needs V[base + ROWS_PER_WARP]
    float2 vnext = make_float2(0.0f, 0.0f);
    if (warp == WARPS_PER_BLOCK - 1) {
        int h = base + ROWS_PER_WARP;
        if (h >= N) h -= N;
        const float4 xh = X4[(size_t)h * 32 + lane];
        float h0 = dot4(xh, xi0);
        float h1 = dot4(xh, xi1);
        float H0, H1, D0, D1;
        quad_reduce(h0, h1, 0.0f, 0.0f, lane, H0, H1, D0, D1);
        vnext = make_float2(fmaxf(H0 + gb0, 0.0f), fmaxf(H1 + gb1, 0.0f));
    }
    __syncthreads();

    if (lane == 0) {
        if (warp < WARPS_PER_BLOCK - 1)
            vnext = Vfirst[warp + 1];
        float2 o;
        o.x = wd_p * v0_p + ws_p * vnext.x;
        o.y = wd_p * v1_p + ws_p * vnext.y;
        reinterpret_cast<float2*>(out)[base + ROWS_PER_WARP - 1] = o;
    }
}

extern "C" void kernel_launch(void* const* d_in, const int* in_sizes, int n_in,
                              void* d_out, int out_size)
{
    const float* X      = (const float*)d_in[0];
    const float* theta  = (const float*)d_in[1];
    const float* f_bias = (const float*)d_in[2];
    const float* xi     = (const float*)d_in[3];
    const float* g_bias = (const float*)d_in[4];
    float* out = (float*)d_out;

    const int N = in_sizes[2];                   // f_bias has N elements
    const int blocks = N / ROWS_PER_BLOCK;       // 524288 / 64 = 8192

    smf_kernel<<<blocks, WARPS_PER_BLOCK * 32>>>(X, theta, f_bias, xi, g_bias, out, N);
}

// round 5
// speedup vs baseline: 1.3104x; 1.0179x over previous
#include <cuda_runtime.h>
#include <cuda_bf16.h>

#define WARPS_PER_BLOCK 8
#define ROWS_PER_WARP 16
#define ROWS_PER_BLOCK (WARPS_PER_BLOCK * ROWS_PER_WARP)   // 128

__device__ __forceinline__ float dot4(float4 a, float4 b) {
    return a.x*b.x + a.y*b.y + a.z*b.z + a.w*b.w;
}

// Packed reduction of 4 per-lane values across the warp. 9 SHFL total.
// Group mapping after reduction: lanes 0/8/16/24 hold totals of pd/ps/q0/q1.
// PD is returned valid on lane 0 only (it IS the local s there); PS/Q0/Q1 are
// broadcast to all lanes.
__device__ __forceinline__ void quad_reduce(float pd, float ps, float q0, float q1,
                                            int lane,
                                            float& PD, float& PS, float& Q0, float& Q1)
{
    const unsigned FULL = 0xFFFFFFFFu;
    const bool lo16 = (lane & 16) == 0;

    // Stage 1 (XOR 16): low half accumulates {pd,ps}, high half {q0,q1}
    float a  = lo16 ? q0 : pd;
    float b  = lo16 ? q1 : ps;
    float ra = __shfl_xor_sync(FULL, a, 16);
    float rb = __shfl_xor_sync(FULL, b, 16);
    float u  = (lo16 ? pd : q0) + ra;
    float v  = (lo16 ? ps : q1) + rb;

    // Stage 2 (XOR 8): each 8-lane group owns one value
    const bool lo8 = (lane & 8) == 0;
    float c  = lo8 ? v : u;
    float rc = __shfl_xor_sync(FULL, c, 8);
    float s  = (lo8 ? u : v) + rc;

    // Stages 3-5: butterfly within the 8-lane group
    s += __shfl_xor_sync(FULL, s, 4);
    s += __shfl_xor_sync(FULL, s, 2);
    s += __shfl_xor_sync(FULL, s, 1);

    PD = s;                           // valid on lane 0
    PS = __shfl_sync(FULL, s, 8);
    Q0 = __shfl_sync(FULL, s, 16);
    Q1 = __shfl_sync(FULL, s, 24);
}

__global__ __launch_bounds__(WARPS_PER_BLOCK * 32)
void smf_kernel(const float* __restrict__ X,
                const float* __restrict__ theta,
                const float* __restrict__ f_bias,
                const float* __restrict__ xi,
                const float* __restrict__ g_bias,
                float* __restrict__ out,
                int N)
{
    __shared__ float2 Vfirst[WARPS_PER_BLOCK];   // V of each warp's first row

    const int warp = threadIdx.x >> 5;
    const int lane = threadIdx.x & 31;
    const int base = (blockIdx.x * WARPS_PER_BLOCK + warp) * ROWS_PER_WARP;

    const float4* __restrict__ X4  = reinterpret_cast<const float4*>(X);
    const float4* __restrict__ T4  = reinterpret_cast<const float4*>(theta);
    const float4* __restrict__ XI4 = reinterpret_cast<const float4*>(xi);

    const float4 xi0 = XI4[lane];
    const float4 xi1 = XI4[32 + lane];
    const float gb0 = g_bias[0];
    const float gb1 = g_bias[1];

    // ---- Software pipeline, depth 2 ----
    // x0 = X[base+r], x1 = X[base+r+1]
    // t0 = T[base+r], t1 = T[base+r+1], t2 = T[base+r+2]
    float4 x0 = X4[(size_t)base * 32 + lane];
    float4 x1 = X4[(size_t)(base + 1) * 32 + lane];
    float4 t0 = T4[(size_t)base * 32 + lane];
    float4 t1 = T4[(size_t)(base + 1) * 32 + lane];
    float4 t2 = T4[(size_t)(base + 2) * 32 + lane];
    float  fb0 = __ldg(f_bias + base);

    float wd_p = 0.0f, ws_p = 0.0f, v0_p = 0.0f, v1_p = 0.0f;

    #pragma unroll
    for (int r = 0; r < ROWS_PER_WARP; r++) {
        const int row = base + r;
        int rn = row + 1;
        if (rn >= N) rn -= N;

        // Issue loads two iterations ahead
        float4 x2, t3;
        if (r < ROWS_PER_WARP - 2) {
            x2 = X4[(size_t)(row + 2) * 32 + lane];
            int i3 = row + 3;
            if (i3 >= N) i3 -= N;            // only for the very last warp
            t3 = T4[(size_t)i3 * 32 + lane];
        }
        const float fb1 = __ldg(f_bias + rn);

        // Per-lane partials
        float pd = dot4(x0, t0);
        float ps = dot4(x0, t1);
        float q0 = dot4(x0, xi0);
        float q1 = dot4(x0, xi1);

        float PD, PS, Q0, Q1;
        quad_reduce(pd, ps, q0, q1, lane, PD, PS, Q0, Q1);

        // Values below are only consumed on lane 0
        const float wd = fmaxf(PD + fb0, 0.0f);
        const float ws = fmaxf(PS + fb1, 0.0f);
        const float v0 = fmaxf(Q0 + gb0, 0.0f);
        const float v1 = fmaxf(Q1 + gb1, 0.0f);

        if (r == 0) {
            if (lane == 0)
                Vfirst[warp] = make_float2(v0, v1);
        } else if (lane == 0) {
            float2 o;
            o.x = wd_p * v0_p + ws_p * v0;
            o.y = wd_p * v1_p + ws_p * v1;
            reinterpret_cast<float2*>(out)[row - 1] = o;
        }

        wd_p = wd; ws_p = ws; v0_p = v0; v1_p = v1;
        fb0 = fb1;
        x0 = x1;
        if (r < ROWS_PER_WARP - 2) x1 = x2;
        t0 = t1; t1 = t2;
        if (r < ROWS_PER_WARP - 2) t2 = t3;
    }

    // Final row of this warp needs V[base + ROWS_PER_WARP]
    float2 vnext = make_float2(0.0f, 0.0f);
    if (warp == WARPS_PER_BLOCK - 1) {
        int h = base + ROWS_PER_WARP;
        if (h >= N) h -= N;
        const float4 xh = X4[(size_t)h * 32 + lane];
        float h0 = dot4(xh, xi0);
        float h1 = dot4(xh, xi1);
        float H0, H1, D0, D1;
        quad_reduce(h0, h1, 0.0f, 0.0f, lane, H0, H1, D0, D1);
        // H0 valid on lane 0; H1 broadcast
        if (lane == 0)
            vnext = make_float2(fmaxf(H0 + gb0, 0.0f), fmaxf(H1 + gb1, 0.0f));
    }
    __syncthreads();

    if (lane == 0) {
        if (warp < WARPS_PER_BLOCK - 1)
            vnext = Vfirst[warp + 1];
        float2 o;
        o.x = wd_p * v0_p + ws_p * vnext.x;
        o.y = wd_p * v1_p + ws_p * vnext.y;
        reinterpret_cast<float2*>(out)[base + ROWS_PER_WARP - 1] = o;
    }
}

extern "C" void kernel_launch(void* const* d_in, const int* in_sizes, int n_in,
                              void* d_out, int out_size)
{
    const float* X      = (const float*)d_in[0];
    const float* theta  = (const float*)d_in[1];
    const float* f_bias = (const float*)d_in[2];
    const float* xi     = (const float*)d_in[3];
    const float* g_bias = (const float*)d_in[4];
    float* out = (float*)d_out;

    const int N = in_sizes[2];                   // f_bias has N elements
    const int blocks = N / ROWS_PER_BLOCK;       // 524288 / 128 = 4096

    smf_kernel<<<blocks, WARPS_PER_BLOCK * 32>>>(X, theta, f_bias, xi, g_bias, out, N);
}